// round 15
// baseline (speedup 1.0000x reference)
#include <cuda_runtime.h>
#include <cstdint>

#define HD  128
#define NL  4
#define BM  128
#define S2  132   // A smem k-stride (words): mod 32 == 4 -> conflict-free frags
#define SB  68    // B half-chunk stride (proj only)

__device__ float g_radial[800000];
__device__ float g_agg[50000 * HD];
__device__ float g_Pa[50000 * HD];
__device__ float g_Pb[50000 * HD];
// pre-transposed tf32 weights: [layer][chunk][n*128+k]
// 0: ew1 0-127  1: ew1 128-255  2: ew2  3: nw1 0-127  4: nw1 128-255  5: nw2
__device__ uint32_t g_WT[NL * 6 * 128 * 128];

__device__ __forceinline__ float silu_f(float v) {
    return __fdividef(v, 1.0f + __expf(-v));
}
__device__ __forceinline__ uint32_t f2tf(float f) {
    uint32_t r;
    asm("cvt.rna.tf32.f32 %0, %1;" : "=r"(r) : "f"(f));
    return r;
}
__device__ __forceinline__ void mma8(float* d, const uint32_t* a, const uint32_t* b) {
    asm volatile(
        "mma.sync.aligned.m16n8k8.row.col.f32.tf32.tf32.f32 "
        "{%0,%1,%2,%3}, {%4,%5,%6,%7}, {%8,%9}, {%0,%1,%2,%3};"
        : "+f"(d[0]), "+f"(d[1]), "+f"(d[2]), "+f"(d[3])
        : "r"(a[0]), "r"(a[1]), "r"(a[2]), "r"(a[3]), "r"(b[0]), "r"(b[1]));
}
__device__ __forceinline__ void red_v4(float* p, float a, float b, float c, float d) {
    asm volatile("red.global.add.v4.f32 [%0], {%1, %2, %3, %4};"
                 :: "l"(p), "f"(a), "f"(b), "f"(c), "f"(d) : "memory");
}

// ---------------------------------------------------------------------------
__global__ void wtrans_kernel(const float* __restrict__ ew1, const float* __restrict__ ew2,
                              const float* __restrict__ nw1, const float* __restrict__ nw2) {
    int idx = blockIdx.x * 256 + threadIdx.x;
    int n = idx >> 7, k = idx & 127;
    int chunk = blockIdx.y;
    int l = chunk / 6, s = chunk - l * 6;
    const float* src;
    switch (s) {
        case 0: src = ew1 + (size_t)l * 261 * HD;            break;
        case 1: src = ew1 + (size_t)l * 261 * HD + 128 * HD; break;
        case 2: src = ew2 + (size_t)l * HD * HD;             break;
        case 3: src = nw1 + (size_t)l * 267 * HD;            break;
        case 4: src = nw1 + (size_t)l * 267 * HD + 128 * HD; break;
        default: src = nw2 + (size_t)l * HD * HD;            break;
    }
    g_WT[(size_t)chunk * 16384 + (size_t)n * 128 + k] = f2tf(src[(size_t)k * HD + n]);
}

// full chunk -> smem, stride S2
__device__ __forceinline__ void stage_wt(uint32_t* Bs, int chunk, int tid) {
    const uint4* src = (const uint4*)(g_WT + (size_t)chunk * 16384);
#pragma unroll 4
    for (int idx = tid; idx < 4096; idx += 256) {
        int n = idx >> 5, g4 = idx & 31;
        *(uint4*)(Bs + n * S2 + g4 * 4) = src[idx];
    }
}
// 64-k half chunk -> smem, stride SB (proj)
__device__ __forceinline__ void stage_wt_half(uint32_t* Bs, int chunk, int kh, int tid) {
    const uint4* src = (const uint4*)(g_WT + (size_t)chunk * 16384);
#pragma unroll 2
    for (int idx = tid; idx < 2048; idx += 256) {
        int n = idx >> 4, q = idx & 15;
        *(uint4*)(Bs + n * SB + q * 4) = src[n * 32 + kh * 16 + q];
    }
}

// ---------------------------------------------------------------------------
__global__ void radial_kernel(const float* __restrict__ x, const int* __restrict__ ei, int E) {
    int e = blockIdx.x * blockDim.x + threadIdx.x;
    if (e >= E) return;
    int r = ei[e], c = ei[E + e];
    float dx = x[r * 3 + 0] - x[c * 3 + 0];
    float dy = x[r * 3 + 1] - x[c * 3 + 1];
    float dz = x[r * 3 + 2] - x[c * 3 + 2];
    g_radial[e] = dx * dx + dy * dy + dz * dz;
}

__global__ void embed_kernel(const float* __restrict__ h0, const float* __restrict__ w,
                             const float* __restrict__ b, float* __restrict__ h) {
    __shared__ float s[11];
    int n = blockIdx.x;
    int f = threadIdx.x;
    if (f < 11) s[f] = h0[n * 11 + f];
    __syncthreads();
    float acc = b[f];
#pragma unroll
    for (int k = 0; k < 11; k++) acc += s[k] * w[k * HD + f];
    h[n * HD + f] = acc;
}

__global__ void zero_agg_kernel(int n4) {
    int i = blockIdx.x * blockDim.x + threadIdx.x;
    if (i < n4) reinterpret_cast<float4*>(g_agg)[i] = make_float4(0.f, 0.f, 0.f, 0.f);
}

// ---------------------------------------------------------------------------
// proj (split-B, 2 CTAs/SM — measured faster in R13)
// ---------------------------------------------------------------------------
#define PROJ_SMEM (512 + 67584 + 34816)
__global__ void __launch_bounds__(256, 2) proj_kernel(
    const float* __restrict__ h, const float* __restrict__ b1,
    int wchunk, int N) {
    extern __shared__ char sm[];
    float*    b1s = (float*)sm;
    uint32_t* As  = (uint32_t*)(sm + 512);
    uint32_t* Bs  = (uint32_t*)(sm + 512 + 67584);

    int tid = threadIdx.x;
    int r0 = blockIdx.x * 128;
    if (tid < 128) b1s[tid] = b1[tid];

    for (int idx = tid; idx < 4096; idx += 256) {
        int row = idx & 127, kg = idx >> 7;
        int gr = r0 + row; if (gr >= N) gr = N - 1;
        float4 v = *(const float4*)(h + (size_t)gr * HD + kg * 4);
        uint4 u = make_uint4(f2tf(v.x), f2tf(v.y), f2tf(v.z), f2tf(v.w));
        *(uint4*)(As + row * S2 + kg * 4) = u;
    }

    int lane = tid & 31, wid = tid >> 5;
    int g = lane >> 2, tg = lane & 3;
    int wm = wid & 1, wn = wid >> 1;

    for (int rep = 0; rep < 2; rep++) {
        float acc[4][4][4];
#pragma unroll
        for (int mt = 0; mt < 4; mt++)
#pragma unroll
            for (int nt = 0; nt < 4; nt++)
#pragma unroll
                for (int q = 0; q < 4; q++) acc[mt][nt][q] = 0.f;

        for (int kh = 0; kh < 2; kh++) {
            __syncthreads();
            stage_wt_half(Bs, wchunk + rep, kh, tid);
            __syncthreads();
#pragma unroll 1
            for (int kc = 0; kc < 8; kc++) {
                int kb = kc * 8;
                int ka = kh * 64 + kb;
                uint32_t a[4][4];
#pragma unroll
                for (int mt = 0; mt < 4; mt++) {
                    int rr = wm * 64 + mt * 16 + g;
                    a[mt][0] = As[rr * S2 + ka + tg];
                    a[mt][1] = As[(rr + 8) * S2 + ka + tg];
                    a[mt][2] = As[rr * S2 + ka + tg + 4];
                    a[mt][3] = As[(rr + 8) * S2 + ka + tg + 4];
                }
#pragma unroll
                for (int nt = 0; nt < 4; nt++) {
                    int cc = wn * 32 + nt * 8 + g;
                    uint32_t b[2] = { Bs[cc * SB + kb + tg], Bs[cc * SB + kb + tg + 4] };
#pragma unroll
                    for (int mt = 0; mt < 4; mt++) mma8(acc[mt][nt], a[mt], b);
                }
            }
        }

        float* out = rep ? g_Pb : g_Pa;
#pragma unroll
        for (int mt = 0; mt < 4; mt++) {
#pragma unroll
            for (int nt = 0; nt < 4; nt++) {
                int col = wn * 32 + nt * 8 + 2 * tg;
                int rr = wm * 64 + mt * 16 + g;
                float bb0 = rep ? 0.f : b1s[col];
                float bb1 = rep ? 0.f : b1s[col + 1];
                if (r0 + rr < N)
                    *(float2*)(out + (size_t)(r0 + rr) * HD + col) =
                        make_float2(acc[mt][nt][0] + bb0, acc[mt][nt][1] + bb1);
                if (r0 + rr + 8 < N)
                    *(float2*)(out + (size_t)(r0 + rr + 8) * HD + col) =
                        make_float2(acc[mt][nt][2] + bb0, acc[mt][nt][3] + bb1);
            }
        }
    }
}

// ---------------------------------------------------------------------------
// Edge (R11 full-B form) + smem-staged red.v4 scatter
// ---------------------------------------------------------------------------
#define EO_RS 0
#define EO_CS 512
#define EO_MS 1024
#define EO_B2 1536
#define EO_T  2048
#define EO_A  4864
#define EO_B  (4864 + 67584)
#define EDGE_SMEM (4864 + 2 * 67584)

__global__ void __launch_bounds__(256, 1) edge2_kernel(
    const float* __restrict__ edge_attr, const float* __restrict__ edge_mask,
    const int* __restrict__ ei, const float* __restrict__ W1,
    const float* __restrict__ b2, int wchunk, int E) {
    extern __shared__ char sm[];
    int*      rs  = (int*)(sm + EO_RS);
    int*      cs  = (int*)(sm + EO_CS);
    float*    ms  = (float*)(sm + EO_MS);
    float*    b2s = (float*)(sm + EO_B2);
    float*    Ts  = (float*)(sm + EO_T);
    uint32_t* As  = (uint32_t*)(sm + EO_A);
    uint32_t* Bs  = (uint32_t*)(sm + EO_B);

    int tid = threadIdx.x;
    int e0 = blockIdx.x * BM;

    if (tid < 128) {
        int ge = e0 + tid;
        int r = 0, c = 0; float mk = 0.f;
        if (ge < E) { r = ei[ge]; c = ei[E + ge]; mk = edge_mask[ge]; }
        rs[tid] = r; cs[tid] = c; ms[tid] = mk;
        b2s[tid] = b2[tid];
    }
    if (tid < 160) {
        int i = tid >> 5, j = (tid & 31) * 4;
        *(float4*)(Ts + i * 128 + j) = *(const float4*)(W1 + (size_t)(256 + i) * HD + j);
    }
    stage_wt(Bs, wchunk + 2, tid);
    __syncthreads();

    {
        int e = tid & 127, jh = (tid >> 7) * 64;
        int ge = e0 + e;
        int gec = (ge < E) ? ge : 0;
        float rad = g_radial[gec];
        float4 ea = *(const float4*)(edge_attr + (size_t)gec * 4);
        const float* pa = g_Pa + (size_t)rs[e] * HD + jh;
        const float* pb = g_Pb + (size_t)cs[e] * HD + jh;
#pragma unroll 4
        for (int i = 0; i < 16; i++) {
            int j = i * 4;
            float4 va = *(const float4*)(pa + j);
            float4 vb = *(const float4*)(pb + j);
            float4 t0 = *(const float4*)(Ts + 0 * 128 + jh + j);
            float4 t1 = *(const float4*)(Ts + 1 * 128 + jh + j);
            float4 t2 = *(const float4*)(Ts + 2 * 128 + jh + j);
            float4 t3 = *(const float4*)(Ts + 3 * 128 + jh + j);
            float4 t4 = *(const float4*)(Ts + 4 * 128 + jh + j);
            float mx = va.x + vb.x + rad * t0.x + ea.x * t1.x + ea.y * t2.x + ea.z * t3.x + ea.w * t4.x;
            float my = va.y + vb.y + rad * t0.y + ea.x * t1.y + ea.y * t2.y + ea.z * t3.y + ea.w * t4.y;
            float mz = va.z + vb.z + rad * t0.z + ea.x * t1.z + ea.y * t2.z + ea.z * t3.z + ea.w * t4.z;
            float mw = va.w + vb.w + rad * t0.w + ea.x * t1.w + ea.y * t2.w + ea.z * t3.w + ea.w * t4.w;
            uint4 u = make_uint4(f2tf(silu_f(mx)), f2tf(silu_f(my)),
                                 f2tf(silu_f(mz)), f2tf(silu_f(mw)));
            *(uint4*)(As + e * S2 + jh + j) = u;
        }
    }
    __syncthreads();

    int lane = tid & 31, wid = tid >> 5;
    int g = lane >> 2, tg = lane & 3;
    int wm = wid & 1, wn = wid >> 1;

    float acc[4][4][4];
#pragma unroll
    for (int mt = 0; mt < 4; mt++)
#pragma unroll
        for (int nt = 0; nt < 4; nt++)
#pragma unroll
            for (int q = 0; q < 4; q++) acc[mt][nt][q] = 0.f;

#pragma unroll 1
    for (int kc = 0; kc < 16; kc++) {
        int kb = kc * 8;
        uint32_t a[4][4];
#pragma unroll
        for (int mt = 0; mt < 4; mt++) {
            int rr = wm * 64 + mt * 16 + g;
            a[mt][0] = As[rr * S2 + kb + tg];
            a[mt][1] = As[(rr + 8) * S2 + kb + tg];
            a[mt][2] = As[rr * S2 + kb + tg + 4];
            a[mt][3] = As[(rr + 8) * S2 + kb + tg + 4];
        }
#pragma unroll
        for (int nt = 0; nt < 4; nt++) {
            int cc = wn * 32 + nt * 8 + g;
            uint32_t b[2] = { Bs[cc * S2 + kb + tg], Bs[cc * S2 + kb + tg + 4] };
#pragma unroll
            for (int mt = 0; mt < 4; mt++) mma8(acc[mt][nt], a[mt], b);
        }
    }
    __syncthreads();   // all As reads done; reuse as output buffer

    // epilogue: silu(+b2)*mask -> smem (half-offset layout: col<64 at col, else col+4)
    float* Os = (float*)As;
#pragma unroll
    for (int mt = 0; mt < 4; mt++) {
#pragma unroll
        for (int nt = 0; nt < 4; nt++) {
            int col = wn * 32 + nt * 8 + 2 * tg;
            int c0 = col + (col & 64 ? 4 : 0);
            int r0 = wm * 64 + mt * 16 + g;
            int r1 = r0 + 8;
            float bb0 = b2s[col], bb1 = b2s[col + 1];
            float mk0 = ms[r0], mk1 = ms[r1];
            Os[r0 * S2 + c0]     = silu_f(acc[mt][nt][0] + bb0) * mk0;
            Os[r0 * S2 + c0 + 1] = silu_f(acc[mt][nt][1] + bb1) * mk0;
            Os[r1 * S2 + c0]     = silu_f(acc[mt][nt][2] + bb0) * mk1;
            Os[r1 * S2 + c0 + 1] = silu_f(acc[mt][nt][3] + bb1) * mk1;
        }
    }
    __syncthreads();

    // scatter: thread handles (edge = tid>>1, half = tid&1), 16 x red.v4
    {
        int e = tid >> 1, hf = tid & 1;
        if (e0 + e < E) {
            const float* src = Os + e * S2 + hf * 68;
            float* dst = g_agg + (size_t)rs[e] * HD + hf * 64;
#pragma unroll
            for (int j = 0; j < 16; j++) {
                float4 v = *(const float4*)(src + j * 4);
                red_v4(dst + j * 4, v.x, v.y, v.z, v.w);
            }
        }
    }
}

// ---------------------------------------------------------------------------
// Node model (R11 full-B form)
// ---------------------------------------------------------------------------
#define NO_B1 0
#define NO_B2 512
#define NO_H0 1024
#define NO_TN 7168
#define NO_A  12800
#define NO_B  (12800 + 67584)
#define NODE_SMEM (12800 + 2 * 67584)

__global__ void __launch_bounds__(256, 1) node_mma_kernel(
    float* __restrict__ h, const float* __restrict__ h0,
    const float* __restrict__ W1, const float* __restrict__ b1,
    const float* __restrict__ b2, int wchunk, int N) {
    extern __shared__ char sm[];
    float*    b1s = (float*)(sm + NO_B1);
    float*    b2s = (float*)(sm + NO_B2);
    float*    h0s = (float*)(sm + NO_H0);
    float*    Tn  = (float*)(sm + NO_TN);
    uint32_t* As  = (uint32_t*)(sm + NO_A);
    uint32_t* Bs  = (uint32_t*)(sm + NO_B);

    int tid = threadIdx.x;
    int r0 = blockIdx.x * 128;
    if (tid < 128) { b1s[tid] = b1[tid]; b2s[tid] = b2[tid]; }
    {
        int row = tid & 127, half = tid >> 7;
        int gr = r0 + row; if (gr >= N) gr = N - 1;
        const float* src = h0 + (size_t)gr * 11;
#pragma unroll
        for (int q = 0; q < 6; q++) {
            int k = half * 6 + q;
            if (k < 11) h0s[row * 12 + k] = src[k];
        }
    }
    for (int idx = tid; idx < 11 * 32; idx += 256) {
        int i = idx >> 5, j = (idx & 31) * 4;
        *(float4*)(Tn + i * 128 + j) = *(const float4*)(W1 + (size_t)(256 + i) * HD + j);
    }

    int lane = tid & 31, wid = tid >> 5;
    int g = lane >> 2, tg = lane & 3;
    int wm = wid & 1, wn = wid >> 1;

    float acc[4][4][4];
#pragma unroll
    for (int mt = 0; mt < 4; mt++)
#pragma unroll
        for (int nt = 0; nt < 4; nt++)
#pragma unroll
            for (int q = 0; q < 4; q++) acc[mt][nt][q] = 0.f;

    for (int rep = 0; rep < 2; rep++) {
        __syncthreads();
        const float* src = rep ? g_agg : h;
        for (int idx = tid; idx < 4096; idx += 256) {
            int row = idx & 127, kg = idx >> 7;
            int gr = r0 + row; if (gr >= N) gr = N - 1;
            float4 v = *(const float4*)(src + (size_t)gr * HD + kg * 4);
            uint4 u = make_uint4(f2tf(v.x), f2tf(v.y), f2tf(v.z), f2tf(v.w));
            *(uint4*)(As + row * S2 + kg * 4) = u;
        }
        stage_wt(Bs, wchunk + 3 + rep, tid);
        __syncthreads();

#pragma unroll 1
        for (int kc = 0; kc < 16; kc++) {
            int kb = kc * 8;
            uint32_t a[4][4];
#pragma unroll
            for (int mt = 0; mt < 4; mt++) {
                int rr = wm * 64 + mt * 16 + g;
                a[mt][0] = As[rr * S2 + kb + tg];
                a[mt][1] = As[(rr + 8) * S2 + kb + tg];
                a[mt][2] = As[rr * S2 + kb + tg + 4];
                a[mt][3] = As[(rr + 8) * S2 + kb + tg + 4];
            }
#pragma unroll
            for (int nt = 0; nt < 4; nt++) {
                int cc = wn * 32 + nt * 8 + g;
                uint32_t b[2] = { Bs[cc * S2 + kb + tg], Bs[cc * S2 + kb + tg + 4] };
#pragma unroll
                for (int mt = 0; mt < 4; mt++) mma8(acc[mt][nt], a[mt], b);
            }
        }
    }
    __syncthreads();

#pragma unroll
    for (int mt = 0; mt < 4; mt++) {
        int rr = wm * 64 + mt * 16 + g;
#pragma unroll
        for (int nt = 0; nt < 4; nt++) {
            int col = wn * 32 + nt * 8 + 2 * tg;
            float v[4];
            v[0] = acc[mt][nt][0] + b1s[col];
            v[1] = acc[mt][nt][1] + b1s[col + 1];
            v[2] = acc[mt][nt][2] + b1s[col];
            v[3] = acc[mt][nt][3] + b1s[col + 1];
#pragma unroll
            for (int k = 0; k < 11; k++) {
                float t0 = Tn[k * 128 + col];
                float t1 = Tn[k * 128 + col + 1];
                float a0 = h0s[rr * 12 + k];
                float a1 = h0s[(rr + 8) * 12 + k];
                v[0] += a0 * t0; v[1] += a0 * t1;
                v[2] += a1 * t0; v[3] += a1 * t1;
            }
            As[rr * S2 + col]           = f2tf(silu_f(v[0]));
            As[rr * S2 + col + 1]       = f2tf(silu_f(v[1]));
            As[(rr + 8) * S2 + col]     = f2tf(silu_f(v[2]));
            As[(rr + 8) * S2 + col + 1] = f2tf(silu_f(v[3]));
        }
    }
    stage_wt(Bs, wchunk + 5, tid);
#pragma unroll
    for (int mt = 0; mt < 4; mt++)
#pragma unroll
        for (int nt = 0; nt < 4; nt++)
#pragma unroll
            for (int q = 0; q < 4; q++) acc[mt][nt][q] = 0.f;
    __syncthreads();

#pragma unroll 1
    for (int kc = 0; kc < 16; kc++) {
        int kb = kc * 8;
        uint32_t a[4][4];
#pragma unroll
        for (int mt = 0; mt < 4; mt++) {
            int rr = wm * 64 + mt * 16 + g;
            a[mt][0] = As[rr * S2 + kb + tg];
            a[mt][1] = As[(rr + 8) * S2 + kb + tg];
            a[mt][2] = As[rr * S2 + kb + tg + 4];
            a[mt][3] = As[(rr + 8) * S2 + kb + tg + 4];
        }
#pragma unroll
        for (int nt = 0; nt < 4; nt++) {
            int cc = wn * 32 + nt * 8 + g;
            uint32_t b[2] = { Bs[cc * S2 + kb + tg], Bs[cc * S2 + kb + tg + 4] };
#pragma unroll
            for (int mt = 0; mt < 4; mt++) mma8(acc[mt][nt], a[mt], b);
        }
    }

#pragma unroll
    for (int mt = 0; mt < 4; mt++) {
        int rr = wm * 64 + mt * 16 + g;
#pragma unroll
        for (int nt = 0; nt < 4; nt++) {
            int col = wn * 32 + nt * 8 + 2 * tg;
            float bb0 = b2s[col], bb1 = b2s[col + 1];
            if (r0 + rr < N) {
                float* p = h + (size_t)(r0 + rr) * HD + col;
                float2 old = *(float2*)p;
                *(float2*)p = make_float2(old.x + acc[mt][nt][0] + bb0,
                                          old.y + acc[mt][nt][1] + bb1);
            }
            if (r0 + rr + 8 < N) {
                float* p = h + (size_t)(r0 + rr + 8) * HD + col;
                float2 old = *(float2*)p;
                *(float2*)p = make_float2(old.x + acc[mt][nt][2] + bb0,
                                          old.y + acc[mt][nt][3] + bb1);
            }
        }
    }
}

// ---------------------------------------------------------------------------
extern "C" void kernel_launch(void* const* d_in, const int* in_sizes, int n_in,
                              void* d_out, int out_size) {
    const float* h0        = (const float*)d_in[0];
    const float* x         = (const float*)d_in[1];
    const int*   ei        = (const int*)  d_in[2];
    const float* edge_attr = (const float*)d_in[3];
    const float* edge_mask = (const float*)d_in[5];

    int wi = (in_sizes[6] == 1) ? 7 : 6;
    const float* emb_w = (const float*)d_in[wi + 0];
    const float* emb_b = (const float*)d_in[wi + 1];
    const float* ew1   = (const float*)d_in[wi + 2];
    const float* eb1   = (const float*)d_in[wi + 3];
    const float* ew2   = (const float*)d_in[wi + 4];
    const float* eb2   = (const float*)d_in[wi + 5];
    const float* nw1   = (const float*)d_in[wi + 6];
    const float* nb1   = (const float*)d_in[wi + 7];
    const float* nw2   = (const float*)d_in[wi + 8];
    const float* nb2   = (const float*)d_in[wi + 9];

    float* h = (float*)d_out;
    int N = in_sizes[0] / 11;
    int E = in_sizes[3] / 4;

    cudaFuncSetAttribute(proj_kernel,     cudaFuncAttributeMaxDynamicSharedMemorySize, PROJ_SMEM);
    cudaFuncSetAttribute(edge2_kernel,    cudaFuncAttributeMaxDynamicSharedMemorySize, EDGE_SMEM);
    cudaFuncSetAttribute(node_mma_kernel, cudaFuncAttributeMaxDynamicSharedMemorySize, NODE_SMEM);

    wtrans_kernel<<<dim3(64, 24), 256>>>(ew1, ew2, nw1, nw2);
    radial_kernel<<<(E + 255) / 256, 256>>>(x, ei, E);
    embed_kernel<<<N, HD>>>(h0, emb_w, emb_b, h);

    int n4 = (N * HD) / 4;
    int pblocks = (N + 127) / 128;
    int eblocks = (E + BM - 1) / BM;

    for (int l = 0; l < NL; l++) {
        proj_kernel<<<pblocks, 256, PROJ_SMEM>>>(h, eb1 + l * HD, l * 6, N);
        zero_agg_kernel<<<(n4 + 255) / 256, 256>>>(n4);
        edge2_kernel<<<eblocks, 256, EDGE_SMEM>>>(edge_attr, edge_mask, ei,
                                                  ew1 + (size_t)l * 261 * HD,
                                                  eb2 + l * HD, l * 6, E);
        node_mma_kernel<<<pblocks, 256, NODE_SMEM>>>(h, h0,
                                                     nw1 + (size_t)l * 267 * HD, nb1 + l * HD,
                                                     nb2 + l * HD, l * 6, N);
    }
}

// round 16
// speedup vs baseline: 1.1902x; 1.1902x over previous
#include <cuda_runtime.h>
#include <cstdint>

#define HD  128
#define NL  4
#define BM  256   // edges per block (edge kernel, 512 threads)
#define S2  132   // A smem k-stride (words): mod 32 == 4 -> conflict-free frags
#define SB  68    // B half-chunk stride (words), mod 32 == 4

__device__ float g_radial[800000];
__device__ float g_agg[50000 * HD];
__device__ float g_Pa[50000 * HD];
__device__ float g_Pb[50000 * HD];
// pre-transposed tf32 weights: [layer][chunk][n*128+k]
// 0: ew1 0-127  1: ew1 128-255  2: ew2  3: nw1 0-127  4: nw1 128-255  5: nw2
__device__ uint32_t g_WT[NL * 6 * 128 * 128];

__device__ __forceinline__ float silu_f(float v) {
    return __fdividef(v, 1.0f + __expf(-v));
}
__device__ __forceinline__ uint32_t f2tf(float f) {
    uint32_t r;
    asm("cvt.rna.tf32.f32 %0, %1;" : "=r"(r) : "f"(f));
    return r;
}
__device__ __forceinline__ void mma8(float* d, const uint32_t* a, const uint32_t* b) {
    asm volatile(
        "mma.sync.aligned.m16n8k8.row.col.f32.tf32.tf32.f32 "
        "{%0,%1,%2,%3}, {%4,%5,%6,%7}, {%8,%9}, {%0,%1,%2,%3};"
        : "+f"(d[0]), "+f"(d[1]), "+f"(d[2]), "+f"(d[3])
        : "r"(a[0]), "r"(a[1]), "r"(a[2]), "r"(a[3]), "r"(b[0]), "r"(b[1]));
}
__device__ __forceinline__ void red_v2(float* p, float a, float b) {
    asm volatile("red.global.add.v2.f32 [%0], {%1, %2};"
                 :: "l"(p), "f"(a), "f"(b) : "memory");
}

// ---------------------------------------------------------------------------
__global__ void wtrans_kernel(const float* __restrict__ ew1, const float* __restrict__ ew2,
                              const float* __restrict__ nw1, const float* __restrict__ nw2) {
    int idx = blockIdx.x * 256 + threadIdx.x;
    int n = idx >> 7, k = idx & 127;
    int chunk = blockIdx.y;
    int l = chunk / 6, s = chunk - l * 6;
    const float* src;
    switch (s) {
        case 0: src = ew1 + (size_t)l * 261 * HD;            break;
        case 1: src = ew1 + (size_t)l * 261 * HD + 128 * HD; break;
        case 2: src = ew2 + (size_t)l * HD * HD;             break;
        case 3: src = nw1 + (size_t)l * 267 * HD;            break;
        case 4: src = nw1 + (size_t)l * 267 * HD + 128 * HD; break;
        default: src = nw2 + (size_t)l * HD * HD;            break;
    }
    g_WT[(size_t)chunk * 16384 + (size_t)n * 128 + k] = f2tf(src[(size_t)k * HD + n]);
}

// full chunk -> smem, stride S2 (node kernel, 256 threads)
__device__ __forceinline__ void stage_wt(uint32_t* Bs, int chunk, int tid) {
    const uint4* src = (const uint4*)(g_WT + (size_t)chunk * 16384);
#pragma unroll 4
    for (int idx = tid; idx < 4096; idx += 256) {
        int n = idx >> 5, g4 = idx & 31;
        *(uint4*)(Bs + n * S2 + g4 * 4) = src[idx];
    }
}
// 64-k half chunk -> smem, stride SB
template <int NT>
__device__ __forceinline__ void stage_wt_half(uint32_t* Bs, int chunk, int kh, int tid) {
#pragma unroll
    for (int idx = tid; idx < 2048; idx += NT) {
        int n = idx >> 4, q = idx & 15;
        *(uint4*)(Bs + n * SB + q * 4) =
            ((const uint4*)(g_WT + (size_t)chunk * 16384))[n * 32 + kh * 16 + q];
    }
}

// ---------------------------------------------------------------------------
__global__ void radial_kernel(const float* __restrict__ x, const int* __restrict__ ei, int E) {
    int e = blockIdx.x * blockDim.x + threadIdx.x;
    if (e >= E) return;
    int r = ei[e], c = ei[E + e];
    float dx = x[r * 3 + 0] - x[c * 3 + 0];
    float dy = x[r * 3 + 1] - x[c * 3 + 1];
    float dz = x[r * 3 + 2] - x[c * 3 + 2];
    g_radial[e] = dx * dx + dy * dy + dz * dz;
}

__global__ void embed_kernel(const float* __restrict__ h0, const float* __restrict__ w,
                             const float* __restrict__ b, float* __restrict__ h) {
    __shared__ float s[11];
    int n = blockIdx.x;
    int f = threadIdx.x;
    if (f < 11) s[f] = h0[n * 11 + f];
    __syncthreads();
    float acc = b[f];
#pragma unroll
    for (int k = 0; k < 11; k++) acc += s[k] * w[k * HD + f];
    h[n * HD + f] = acc;
}

// ---------------------------------------------------------------------------
// proj (split-B, 2 CTAs/SM) + fused zero of this block's g_agg rows
// ---------------------------------------------------------------------------
#define PROJ_SMEM (512 + 67584 + 34816)
__global__ void __launch_bounds__(256, 2) proj_kernel(
    const float* __restrict__ h, const float* __restrict__ b1,
    int wchunk, int N) {
    extern __shared__ char sm[];
    float*    b1s = (float*)sm;
    uint32_t* As  = (uint32_t*)(sm + 512);
    uint32_t* Bs  = (uint32_t*)(sm + 512 + 67584);

    int tid = threadIdx.x;
    int r0 = blockIdx.x * 128;
    if (tid < 128) b1s[tid] = b1[tid];

    // fused zero of g_agg rows [r0, r0+128)
    for (int idx = tid; idx < 4096; idx += 256) {
        int row = idx >> 5, c4 = idx & 31;
        int gr = r0 + row;
        if (gr < N) *(float4*)(g_agg + (size_t)gr * HD + c4 * 4) =
            make_float4(0.f, 0.f, 0.f, 0.f);
    }

    for (int idx = tid; idx < 4096; idx += 256) {
        int row = idx & 127, kg = idx >> 7;
        int gr = r0 + row; if (gr >= N) gr = N - 1;
        float4 v = *(const float4*)(h + (size_t)gr * HD + kg * 4);
        uint4 u = make_uint4(f2tf(v.x), f2tf(v.y), f2tf(v.z), f2tf(v.w));
        *(uint4*)(As + row * S2 + kg * 4) = u;
    }

    int lane = tid & 31, wid = tid >> 5;
    int g = lane >> 2, tg = lane & 3;
    int wm = wid & 1, wn = wid >> 1;

    for (int rep = 0; rep < 2; rep++) {
        float acc[4][4][4];
#pragma unroll
        for (int mt = 0; mt < 4; mt++)
#pragma unroll
            for (int nt = 0; nt < 4; nt++)
#pragma unroll
                for (int q = 0; q < 4; q++) acc[mt][nt][q] = 0.f;

        for (int kh = 0; kh < 2; kh++) {
            __syncthreads();
            stage_wt_half<256>(Bs, wchunk + rep, kh, tid);
            __syncthreads();
#pragma unroll 1
            for (int kc = 0; kc < 8; kc++) {
                int kb = kc * 8;
                int ka = kh * 64 + kb;
                uint32_t a[4][4];
#pragma unroll
                for (int mt = 0; mt < 4; mt++) {
                    int rr = wm * 64 + mt * 16 + g;
                    a[mt][0] = As[rr * S2 + ka + tg];
                    a[mt][1] = As[(rr + 8) * S2 + ka + tg];
                    a[mt][2] = As[rr * S2 + ka + tg + 4];
                    a[mt][3] = As[(rr + 8) * S2 + ka + tg + 4];
                }
#pragma unroll
                for (int nt = 0; nt < 4; nt++) {
                    int cc = wn * 32 + nt * 8 + g;
                    uint32_t b[2] = { Bs[cc * SB + kb + tg], Bs[cc * SB + kb + tg + 4] };
#pragma unroll
                    for (int mt = 0; mt < 4; mt++) mma8(acc[mt][nt], a[mt], b);
                }
            }
        }

        float* out = rep ? g_Pb : g_Pa;
#pragma unroll
        for (int mt = 0; mt < 4; mt++) {
#pragma unroll
            for (int nt = 0; nt < 4; nt++) {
                int col = wn * 32 + nt * 8 + 2 * tg;
                int rr = wm * 64 + mt * 16 + g;
                float bb0 = rep ? 0.f : b1s[col];
                float bb1 = rep ? 0.f : b1s[col + 1];
                if (r0 + rr < N)
                    *(float2*)(out + (size_t)(r0 + rr) * HD + col) =
                        make_float2(acc[mt][nt][0] + bb0, acc[mt][nt][1] + bb1);
                if (r0 + rr + 8 < N)
                    *(float2*)(out + (size_t)(r0 + rr + 8) * HD + col) =
                        make_float2(acc[mt][nt][2] + bb0, acc[mt][nt][3] + bb1);
            }
        }
    }
}

// ---------------------------------------------------------------------------
// Edge: 512 threads, 256 edges/block, 16 warps (warp tile 64x32).
// m1 = silu(Pa[row]+Pb[col]+tail); GEMM2 (split-B); silu(+b2)*mask -> red.v2
// ---------------------------------------------------------------------------
#define E2_RS 0
#define E2_CS 1024
#define E2_MS 2048
#define E2_B2 3072
#define E2_T  3584
#define E2_A  6144
#define E2_B  (6144 + 135168)
#define EDGE_SMEM (6144 + 135168 + 34816)

__global__ void __launch_bounds__(512, 1) edge2_kernel(
    const float* __restrict__ edge_attr, const float* __restrict__ edge_mask,
    const int* __restrict__ ei, const float* __restrict__ W1,
    const float* __restrict__ b2, int wchunk, int E) {
    extern __shared__ char sm[];
    int*      rs  = (int*)(sm + E2_RS);
    int*      cs  = (int*)(sm + E2_CS);
    float*    ms  = (float*)(sm + E2_MS);
    float*    b2s = (float*)(sm + E2_B2);
    float*    Ts  = (float*)(sm + E2_T);
    uint32_t* As  = (uint32_t*)(sm + E2_A);
    uint32_t* Bs  = (uint32_t*)(sm + E2_B);

    int tid = threadIdx.x;
    int e0 = blockIdx.x * BM;

    if (tid < 256) {
        int ge = e0 + tid;
        int r = 0, c = 0; float mk = 0.f;
        if (ge < E) { r = ei[ge]; c = ei[E + ge]; mk = edge_mask[ge]; }
        rs[tid] = r; cs[tid] = c; ms[tid] = mk;
    }
    if (tid < 128) b2s[tid] = b2[tid];
    if (tid < 160) {
        int i = tid >> 5, j = (tid & 31) * 4;
        *(float4*)(Ts + i * 128 + j) = *(const float4*)(W1 + (size_t)(256 + i) * HD + j);
    }
    stage_wt_half<512>(Bs, wchunk + 2, 0, tid);
    __syncthreads();

    // gather + m1: e = tid&255, half = tid>>8
    {
        int e = tid & 255, jh = (tid >> 8) * 64;
        int ge = e0 + e;
        int gec = (ge < E) ? ge : 0;
        float rad = g_radial[gec];
        float4 ea = *(const float4*)(edge_attr + (size_t)gec * 4);
        const float* pa = g_Pa + (size_t)rs[e] * HD + jh;
        const float* pb = g_Pb + (size_t)cs[e] * HD + jh;
#pragma unroll 4
        for (int i = 0; i < 16; i++) {
            int j = i * 4;
            float4 va = *(const float4*)(pa + j);
            float4 vb = *(const float4*)(pb + j);
            float4 t0 = *(const float4*)(Ts + 0 * 128 + jh + j);
            float4 t1 = *(const float4*)(Ts + 1 * 128 + jh + j);
            float4 t2 = *(const float4*)(Ts + 2 * 128 + jh + j);
            float4 t3 = *(const float4*)(Ts + 3 * 128 + jh + j);
            float4 t4 = *(const float4*)(Ts + 4 * 128 + jh + j);
            float mx = va.x + vb.x + rad * t0.x + ea.x * t1.x + ea.y * t2.x + ea.z * t3.x + ea.w * t4.x;
            float my = va.y + vb.y + rad * t0.y + ea.x * t1.y + ea.y * t2.y + ea.z * t3.y + ea.w * t4.y;
            float mz = va.z + vb.z + rad * t0.z + ea.x * t1.z + ea.y * t2.z + ea.z * t3.z + ea.w * t4.z;
            float mw = va.w + vb.w + rad * t0.w + ea.x * t1.w + ea.y * t2.w + ea.z * t3.w + ea.w * t4.w;
            uint4 u = make_uint4(f2tf(silu_f(mx)), f2tf(silu_f(my)),
                                 f2tf(silu_f(mz)), f2tf(silu_f(mw)));
            *(uint4*)(As + e * S2 + jh + j) = u;
        }
    }
    __syncthreads();

    int lane = tid & 31, wid = tid >> 5;
    int g = lane >> 2, tg = lane & 3;
    int wm = wid & 3, wn = wid >> 2;   // 4 x 4 warp grid: M 4x64, N 4x32

    float acc[4][4][4];
#pragma unroll
    for (int mt = 0; mt < 4; mt++)
#pragma unroll
        for (int nt = 0; nt < 4; nt++)
#pragma unroll
            for (int q = 0; q < 4; q++) acc[mt][nt][q] = 0.f;

    for (int kh = 0; kh < 2; kh++) {
        if (kh) {
            __syncthreads();
            stage_wt_half<512>(Bs, wchunk + 2, 1, tid);
            __syncthreads();
        }
#pragma unroll 1
        for (int kc = 0; kc < 8; kc++) {
            int kb = kc * 8;
            int ka = kh * 64 + kb;
            uint32_t a[4][4];
#pragma unroll
            for (int mt = 0; mt < 4; mt++) {
                int rr = wm * 64 + mt * 16 + g;
                a[mt][0] = As[rr * S2 + ka + tg];
                a[mt][1] = As[(rr + 8) * S2 + ka + tg];
                a[mt][2] = As[rr * S2 + ka + tg + 4];
                a[mt][3] = As[(rr + 8) * S2 + ka + tg + 4];
            }
#pragma unroll
            for (int nt = 0; nt < 4; nt++) {
                int cc = wn * 32 + nt * 8 + g;
                uint32_t b[2] = { Bs[cc * SB + kb + tg], Bs[cc * SB + kb + tg + 4] };
#pragma unroll
                for (int mt = 0; mt < 4; mt++) mma8(acc[mt][nt], a[mt], b);
            }
        }
    }

    // epilogue: silu(+b2)*mask -> red.v2 scatter (direct from registers)
#pragma unroll
    for (int mt = 0; mt < 4; mt++) {
#pragma unroll
        for (int nt = 0; nt < 4; nt++) {
            int col = wn * 32 + nt * 8 + 2 * tg;
            int r0 = wm * 64 + mt * 16 + g;
            int r1 = r0 + 8;
            float bb0 = b2s[col], bb1 = b2s[col + 1];
            if (e0 + r0 < E) {
                float mk = ms[r0];
                red_v2(&g_agg[rs[r0] * HD + col],
                       silu_f(acc[mt][nt][0] + bb0) * mk,
                       silu_f(acc[mt][nt][1] + bb1) * mk);
            }
            if (e0 + r1 < E) {
                float mk = ms[r1];
                red_v2(&g_agg[rs[r1] * HD + col],
                       silu_f(acc[mt][nt][2] + bb0) * mk,
                       silu_f(acc[mt][nt][3] + bb1) * mk);
            }
        }
    }
}

// ---------------------------------------------------------------------------
// Node model (R11 full-B form, 256 threads)
// ---------------------------------------------------------------------------
#define NO_B1 0
#define NO_B2 512
#define NO_H0 1024
#define NO_TN 7168
#define NO_A  12800
#define NO_B  (12800 + 67584)
#define NODE_SMEM (12800 + 2 * 67584)

__global__ void __launch_bounds__(256, 1) node_mma_kernel(
    float* __restrict__ h, const float* __restrict__ h0,
    const float* __restrict__ W1, const float* __restrict__ b1,
    const float* __restrict__ b2, int wchunk, int N) {
    extern __shared__ char sm[];
    float*    b1s = (float*)(sm + NO_B1);
    float*    b2s = (float*)(sm + NO_B2);
    float*    h0s = (float*)(sm + NO_H0);
    float*    Tn  = (float*)(sm + NO_TN);
    uint32_t* As  = (uint32_t*)(sm + NO_A);
    uint32_t* Bs  = (uint32_t*)(sm + NO_B);

    int tid = threadIdx.x;
    int r0 = blockIdx.x * 128;
    if (tid < 128) { b1s[tid] = b1[tid]; b2s[tid] = b2[tid]; }
    {
        int row = tid & 127, half = tid >> 7;
        int gr = r0 + row; if (gr >= N) gr = N - 1;
        const float* src = h0 + (size_t)gr * 11;
#pragma unroll
        for (int q = 0; q < 6; q++) {
            int k = half * 6 + q;
            if (k < 11) h0s[row * 12 + k] = src[k];
        }
    }
    for (int idx = tid; idx < 11 * 32; idx += 256) {
        int i = idx >> 5, j = (idx & 31) * 4;
        *(float4*)(Tn + i * 128 + j) = *(const float4*)(W1 + (size_t)(256 + i) * HD + j);
    }

    int lane = tid & 31, wid = tid >> 5;
    int g = lane >> 2, tg = lane & 3;
    int wm = wid & 1, wn = wid >> 1;

    float acc[4][4][4];
#pragma unroll
    for (int mt = 0; mt < 4; mt++)
#pragma unroll
        for (int nt = 0; nt < 4; nt++)
#pragma unroll
            for (int q = 0; q < 4; q++) acc[mt][nt][q] = 0.f;

    for (int rep = 0; rep < 2; rep++) {
        __syncthreads();
        const float* src = rep ? g_agg : h;
        for (int idx = tid; idx < 4096; idx += 256) {
            int row = idx & 127, kg = idx >> 7;
            int gr = r0 + row; if (gr >= N) gr = N - 1;
            float4 v = *(const float4*)(src + (size_t)gr * HD + kg * 4);
            uint4 u = make_uint4(f2tf(v.x), f2tf(v.y), f2tf(v.z), f2tf(v.w));
            *(uint4*)(As + row * S2 + kg * 4) = u;
        }
        stage_wt(Bs, wchunk + 3 + rep, tid);
        __syncthreads();

#pragma unroll 1
        for (int kc = 0; kc < 16; kc++) {
            int kb = kc * 8;
            uint32_t a[4][4];
#pragma unroll
            for (int mt = 0; mt < 4; mt++) {
                int rr = wm * 64 + mt * 16 + g;
                a[mt][0] = As[rr * S2 + kb + tg];
                a[mt][1] = As[(rr + 8) * S2 + kb + tg];
                a[mt][2] = As[rr * S2 + kb + tg + 4];
                a[mt][3] = As[(rr + 8) * S2 + kb + tg + 4];
            }
#pragma unroll
            for (int nt = 0; nt < 4; nt++) {
                int cc = wn * 32 + nt * 8 + g;
                uint32_t b[2] = { Bs[cc * S2 + kb + tg], Bs[cc * S2 + kb + tg + 4] };
#pragma unroll
                for (int mt = 0; mt < 4; mt++) mma8(acc[mt][nt], a[mt], b);
            }
        }
    }
    __syncthreads();

#pragma unroll
    for (int mt = 0; mt < 4; mt++) {
        int rr = wm * 64 + mt * 16 + g;
#pragma unroll
        for (int nt = 0; nt < 4; nt++) {
            int col = wn * 32 + nt * 8 + 2 * tg;
            float v[4];
            v[0] = acc[mt][nt][0] + b1s[col];
            v[1] = acc[mt][nt][1] + b1s[col + 1];
            v[2] = acc[mt][nt][2] + b1s[col];
            v[3] = acc[mt][nt][3] + b1s[col + 1];
#pragma unroll
            for (int k = 0; k < 11; k++) {
                float t0 = Tn[k * 128 + col];
                float t1 = Tn[k * 128 + col + 1];
                float a0 = h0s[rr * 12 + k];
                float a1 = h0s[(rr + 8) * 12 + k];
                v[0] += a0 * t0; v[1] += a0 * t1;
                v[2] += a1 * t0; v[3] += a1 * t1;
            }
            As[rr * S2 + col]           = f2tf(silu_f(v[0]));
            As[rr * S2 + col + 1]       = f2tf(silu_f(v[1]));
            As[(rr + 8) * S2 + col]     = f2tf(silu_f(v[2]));
            As[(rr + 8) * S2 + col + 1] = f2tf(silu_f(v[3]));
        }
    }
    stage_wt(Bs, wchunk + 5, tid);
#pragma unroll
    for (int mt = 0; mt < 4; mt++)
#pragma unroll
        for (int nt = 0; nt < 4; nt++)
#pragma unroll
            for (int q = 0; q < 4; q++) acc[mt][nt][q] = 0.f;
    __syncthreads();

#pragma unroll 1
    for (int kc = 0; kc < 16; kc++) {
        int kb = kc * 8;
        uint32_t a[4][4];
#pragma unroll
        for (int mt = 0; mt < 4; mt++) {
            int rr = wm * 64 + mt * 16 + g;
            a[mt][0] = As[rr * S2 + kb + tg];
            a[mt][1] = As[(rr + 8) * S2 + kb + tg];
            a[mt][2] = As[rr * S2 + kb + tg + 4];
            a[mt][3] = As[(rr + 8) * S2 + kb + tg + 4];
        }
#pragma unroll
        for (int nt = 0; nt < 4; nt++) {
            int cc = wn * 32 + nt * 8 + g;
            uint32_t b[2] = { Bs[cc * S2 + kb + tg], Bs[cc * S2 + kb + tg + 4] };
#pragma unroll
            for (int mt = 0; mt < 4; mt++) mma8(acc[mt][nt], a[mt], b);
        }
    }

#pragma unroll
    for (int mt = 0; mt < 4; mt++) {
        int rr = wm * 64 + mt * 16 + g;
#pragma unroll
        for (int nt = 0; nt < 4; nt++) {
            int col = wn * 32 + nt * 8 + 2 * tg;
            float bb0 = b2s[col], bb1 = b2s[col + 1];
            if (r0 + rr < N) {
                float* p = h + (size_t)(r0 + rr) * HD + col;
                float2 old = *(float2*)p;
                *(float2*)p = make_float2(old.x + acc[mt][nt][0] + bb0,
                                          old.y + acc[mt][nt][1] + bb1);
            }
            if (r0 + rr + 8 < N) {
                float* p = h + (size_t)(r0 + rr + 8) * HD + col;
                float2 old = *(float2*)p;
                *(float2*)p = make_float2(old.x + acc[mt][nt][2] + bb0,
                                          old.y + acc[mt][nt][3] + bb1);
            }
        }
    }
}

// ---------------------------------------------------------------------------
extern "C" void kernel_launch(void* const* d_in, const int* in_sizes, int n_in,
                              void* d_out, int out_size) {
    const float* h0        = (const float*)d_in[0];
    const float* x         = (const float*)d_in[1];
    const int*   ei        = (const int*)  d_in[2];
    const float* edge_attr = (const float*)d_in[3];
    const float* edge_mask = (const float*)d_in[5];

    int wi = (in_sizes[6] == 1) ? 7 : 6;
    const float* emb_w = (const float*)d_in[wi + 0];
    const float* emb_b = (const float*)d_in[wi + 1];
    const float* ew1   = (const float*)d_in[wi + 2];
    const float* eb1   = (const float*)d_in[wi + 3];
    const float* ew2   = (const float*)d_in[wi + 4];
    const float* eb2   = (const float*)d_in[wi + 5];
    const float* nw1   = (const float*)d_in[wi + 6];
    const float* nb1   = (const float*)d_in[wi + 7];
    const float* nw2   = (const float*)d_in[wi + 8];
    const float* nb2   = (const float*)d_in[wi + 9];

    float* h = (float*)d_out;
    int N = in_sizes[0] / 11;
    int E = in_sizes[3] / 4;

    cudaFuncSetAttribute(proj_kernel,     cudaFuncAttributeMaxDynamicSharedMemorySize, PROJ_SMEM);
    cudaFuncSetAttribute(edge2_kernel,    cudaFuncAttributeMaxDynamicSharedMemorySize, EDGE_SMEM);
    cudaFuncSetAttribute(node_mma_kernel, cudaFuncAttributeMaxDynamicSharedMemorySize, NODE_SMEM);

    wtrans_kernel<<<dim3(64, 24), 256>>>(ew1, ew2, nw1, nw2);
    radial_kernel<<<(E + 255) / 256, 256>>>(x, ei, E);
    embed_kernel<<<N, HD>>>(h0, emb_w, emb_b, h);

    int pblocks = (N + 127) / 128;
    int eblocks = (E + BM - 1) / BM;

    for (int l = 0; l < NL; l++) {
        proj_kernel<<<pblocks, 256, PROJ_SMEM>>>(h, eb1 + l * HD, l * 6, N);
        edge2_kernel<<<eblocks, 512, EDGE_SMEM>>>(edge_attr, edge_mask, ei,
                                                  ew1 + (size_t)l * 261 * HD,
                                                  eb2 + l * HD, l * 6, E);
        node_mma_kernel<<<pblocks, 256, NODE_SMEM>>>(h, h0,
                                                     nw1 + (size_t)l * 267 * HD, nb1 + l * HD,
                                                     nb2 + l * HD, l * 6, N);
    }
}